// round 1
// baseline (speedup 1.0000x reference)
#include <cuda_runtime.h>
#include <cuda_bf16.h>

// ---------------------------------------------------------------------------
// DigitConvolutionalModel: x[65536,784] -> conv3x3(valid) -> 676
//   -> relu(fc 676->128) -> relu(fc 128->512) -> relu(fc 512->256) -> fc 256->10
// Inputs (metadata order): x, w_conv, w1, b1, w2, b2, w3, b3, w4, b4
// Output: float32 [65536, 10]
// ---------------------------------------------------------------------------

#define BATCH 65536

// Scratch activations (allocation-free rule: __device__ globals)
__device__ float g_c [BATCH * 676];   // conv output
__device__ float g_h1[BATCH * 128];
__device__ float g_h2[BATCH * 512];
__device__ float g_h3[BATCH * 256];

// ---------------------------------------------------------------------------
// Conv kernel: per sample, c[i,j] = sum_{di,dj} x[i+di, j+dj] * wc[di,dj]
// 4 samples per 256-thread CTA, smem staged.
// ---------------------------------------------------------------------------
#define CONV_S 4
__global__ void conv_kernel(const float* __restrict__ x,
                            const float* __restrict__ wc,
                            float* __restrict__ c)
{
    __shared__ float xs[CONV_S * 784];
    __shared__ float w[9];
    const int tid  = threadIdx.x;
    const int base = blockIdx.x * CONV_S;

    if (tid < 9) w[tid] = wc[tid];
    #pragma unroll
    for (int i = tid; i < CONV_S * 784; i += 256)
        xs[i] = x[(size_t)base * 784 + i];
    __syncthreads();

    #pragma unroll
    for (int idx = tid; idx < CONV_S * 676; idx += 256) {
        int s  = idx / 676;
        int o  = idx - s * 676;
        int oi = o / 26;
        int oj = o - oi * 26;
        const float* p = &xs[s * 784 + oi * 28 + oj];
        float sum = p[0]  * w[0] + p[1]  * w[1] + p[2]  * w[2]
                  + p[28] * w[3] + p[29] * w[4] + p[30] * w[5]
                  + p[56] * w[6] + p[57] * w[7] + p[58] * w[8];
        c[(size_t)base * 676 + idx] = sum;
    }
}

// ---------------------------------------------------------------------------
// Generic NT GEMM + bias + (optional) relu:
//   C[m,n] = relu( sum_k A[m,k] * W[n,k] + bias[n] )
// A: [M,K] row-major, W: [N,K] row-major. BM=128, BN=64, BK=16.
// 256 threads, each computes 8x4 outputs. A tile stored K-major (transposed)
// in smem so compute reads are LDS.128.
// Requires: M % 128 == 0, N % 64 == 0, K % 4 == 0 (K ragged vs 16 is OK).
// ---------------------------------------------------------------------------
template <bool RELU>
__global__ __launch_bounds__(256)
void gemm_nt_bias(const float* __restrict__ A,
                  const float* __restrict__ W,
                  const float* __restrict__ bias,
                  float* __restrict__ C,
                  int M, int N, int K)
{
    __shared__ float As[16 * 128];   // As[k][m]
    __shared__ float Ws[16 * 64];    // Ws[k][n]

    const int tid = threadIdx.x;
    const int tx  = tid & 15;        // N direction (4 cols each)
    const int ty  = tid >> 4;        // M direction (8 rows each)
    const int m0  = blockIdx.y * 128;
    const int n0  = blockIdx.x * 64;

    // A tile loader: two float4 per thread
    const int a_row0 = tid >> 2;           // 0..63
    const int a_c4   = tid & 3;            // which float4 within 16 k's
    // W tile loader: one float4 per thread
    const int w_row  = tid >> 2;           // 0..63
    const int w_c4   = tid & 3;

    float acc[8][4];
    #pragma unroll
    for (int i = 0; i < 8; ++i)
        #pragma unroll
        for (int j = 0; j < 4; ++j) acc[i][j] = 0.f;

    for (int kt = 0; kt < K; kt += 16) {
        // ---- load A tile (128 x 16) ----
        {
            const int kk = kt + a_c4 * 4;
            const bool ok = kk < K;   // K % 4 == 0 so whole float4 valid or not
            float4 v0 = make_float4(0.f, 0.f, 0.f, 0.f);
            float4 v1 = v0;
            if (ok) {
                v0 = *reinterpret_cast<const float4*>(
                        &A[(size_t)(m0 + a_row0) * K + kk]);
                v1 = *reinterpret_cast<const float4*>(
                        &A[(size_t)(m0 + a_row0 + 64) * K + kk]);
            }
            const int kb = a_c4 * 4;
            As[(kb + 0) * 128 + a_row0] = v0.x;
            As[(kb + 1) * 128 + a_row0] = v0.y;
            As[(kb + 2) * 128 + a_row0] = v0.z;
            As[(kb + 3) * 128 + a_row0] = v0.w;
            As[(kb + 0) * 128 + a_row0 + 64] = v1.x;
            As[(kb + 1) * 128 + a_row0 + 64] = v1.y;
            As[(kb + 2) * 128 + a_row0 + 64] = v1.z;
            As[(kb + 3) * 128 + a_row0 + 64] = v1.w;
        }
        // ---- load W tile (64 x 16) ----
        {
            const int kk = kt + w_c4 * 4;
            float4 v = make_float4(0.f, 0.f, 0.f, 0.f);
            if (kk < K)
                v = *reinterpret_cast<const float4*>(
                        &W[(size_t)(n0 + w_row) * K + kk]);
            const int kb = w_c4 * 4;
            Ws[(kb + 0) * 64 + w_row] = v.x;
            Ws[(kb + 1) * 64 + w_row] = v.y;
            Ws[(kb + 2) * 64 + w_row] = v.z;
            Ws[(kb + 3) * 64 + w_row] = v.w;
        }
        __syncthreads();

        #pragma unroll
        for (int k = 0; k < 16; ++k) {
            float4 a0 = *reinterpret_cast<const float4*>(&As[k * 128 + ty * 8]);
            float4 a1 = *reinterpret_cast<const float4*>(&As[k * 128 + ty * 8 + 4]);
            float4 wv = *reinterpret_cast<const float4*>(&Ws[k * 64 + tx * 4]);
            const float aa[8] = {a0.x, a0.y, a0.z, a0.w, a1.x, a1.y, a1.z, a1.w};
            const float ww[4] = {wv.x, wv.y, wv.z, wv.w};
            #pragma unroll
            for (int i = 0; i < 8; ++i)
                #pragma unroll
                for (int j = 0; j < 4; ++j)
                    acc[i][j] = fmaf(aa[i], ww[j], acc[i][j]);
        }
        __syncthreads();
    }

    // ---- epilogue: bias (+relu), vectorized store ----
    const int cn = n0 + tx * 4;
    float4 bv = *reinterpret_cast<const float4*>(&bias[cn]);
    #pragma unroll
    for (int i = 0; i < 8; ++i) {
        float4 r;
        r.x = acc[i][0] + bv.x;
        r.y = acc[i][1] + bv.y;
        r.z = acc[i][2] + bv.z;
        r.w = acc[i][3] + bv.w;
        if (RELU) {
            r.x = fmaxf(r.x, 0.f);
            r.y = fmaxf(r.y, 0.f);
            r.z = fmaxf(r.z, 0.f);
            r.w = fmaxf(r.w, 0.f);
        }
        *reinterpret_cast<float4*>(&C[(size_t)(m0 + ty * 8 + i) * N + cn]) = r;
    }
}

// ---------------------------------------------------------------------------
// Head: out[m, 0..9] = h3[m, :] @ w4[0..9, :]^T + b4.   K=256, N=10.
// Warp per row; lanes split K; butterfly reduce.
// ---------------------------------------------------------------------------
__global__ __launch_bounds__(256)
void head_kernel(const float* __restrict__ h3,
                 const float* __restrict__ w4,
                 const float* __restrict__ b4,
                 float* __restrict__ out)
{
    __shared__ float ws[10 * 256];
    __shared__ float bs[10];
    const int tid = threadIdx.x;
    #pragma unroll
    for (int i = tid; i < 2560; i += 256) ws[i] = w4[i];
    if (tid < 10) bs[tid] = b4[tid];
    __syncthreads();

    const int warp = tid >> 5;
    const int lane = tid & 31;
    const int row  = blockIdx.x * 8 + warp;

    float acc[10];
    #pragma unroll
    for (int j = 0; j < 10; ++j) acc[j] = 0.f;

    const float* hr = h3 + (size_t)row * 256;
    #pragma unroll
    for (int t = 0; t < 8; ++t) {
        float xv = hr[t * 32 + lane];
        #pragma unroll
        for (int j = 0; j < 10; ++j)
            acc[j] = fmaf(xv, ws[j * 256 + t * 32 + lane], acc[j]);
    }
    #pragma unroll
    for (int j = 0; j < 10; ++j) {
        #pragma unroll
        for (int off = 16; off > 0; off >>= 1)
            acc[j] += __shfl_xor_sync(0xffffffffu, acc[j], off);
    }
    if (lane == 0) {
        #pragma unroll
        for (int j = 0; j < 10; ++j)
            out[(size_t)row * 10 + j] = acc[j] + bs[j];
    }
}

// ---------------------------------------------------------------------------
// Launch
// ---------------------------------------------------------------------------
extern "C" void kernel_launch(void* const* d_in, const int* in_sizes, int n_in,
                              void* d_out, int out_size)
{
    const float* x  = (const float*)d_in[0];
    const float* wc = (const float*)d_in[1];
    const float* w1 = (const float*)d_in[2];
    const float* b1 = (const float*)d_in[3];
    const float* w2 = (const float*)d_in[4];
    const float* b2 = (const float*)d_in[5];
    const float* w3 = (const float*)d_in[6];
    const float* b3 = (const float*)d_in[7];
    const float* w4 = (const float*)d_in[8];
    const float* b4 = (const float*)d_in[9];
    float* out = (float*)d_out;

    float *c, *h1, *h2, *h3;
    cudaGetSymbolAddress((void**)&c,  g_c);
    cudaGetSymbolAddress((void**)&h1, g_h1);
    cudaGetSymbolAddress((void**)&h2, g_h2);
    cudaGetSymbolAddress((void**)&h3, g_h3);

    conv_kernel<<<BATCH / CONV_S, 256>>>(x, wc, c);

    // L1: [65536,676] x [128,676]^T -> relu -> h1
    gemm_nt_bias<true><<<dim3(128 / 64, BATCH / 128), 256>>>(c,  w1, b1, h1, BATCH, 128, 676);
    // L2: [65536,128] x [512,128]^T -> relu -> h2
    gemm_nt_bias<true><<<dim3(512 / 64, BATCH / 128), 256>>>(h1, w2, b2, h2, BATCH, 512, 128);
    // L3: [65536,512] x [256,512]^T -> relu -> h3
    gemm_nt_bias<true><<<dim3(256 / 64, BATCH / 128), 256>>>(h2, w3, b3, h3, BATCH, 256, 512);
    // L4: [65536,256] x [10,256]^T -> out
    head_kernel<<<BATCH / 8, 256>>>(h3, w4, b4, out);
}

// round 4
// speedup vs baseline: 1.8895x; 1.8895x over previous
#include <cuda_runtime.h>
#include <cuda_bf16.h>
#include <cstdint>

// ---------------------------------------------------------------------------
// DigitConvolutionalModel via mma.sync bf16 split-precision (bf16x3) GEMMs.
// (tcgen05 unavailable: harness PTX target is compute_103, no 'a' features.)
// x[65536,784] -> conv3x3 -> 676(pad 704) -> fc 128 -> fc 512 -> fc 256 -> fc 10
// ---------------------------------------------------------------------------

#define BATCH 65536
#define K1P   704

// ---- scratch (__device__ globals; no allocations allowed) ----
__device__ __nv_bfloat16 g_c_hi [BATCH * K1P];
__device__ __nv_bfloat16 g_c_lo [BATCH * K1P];
__device__ __nv_bfloat16 g_h1_hi[BATCH * 128];
__device__ __nv_bfloat16 g_h1_lo[BATCH * 128];
__device__ __nv_bfloat16 g_h2_hi[BATCH * 512];
__device__ __nv_bfloat16 g_h2_lo[BATCH * 512];
__device__ float         g_h3   [BATCH * 256];
__device__ __nv_bfloat16 g_w1_hi[128 * K1P];
__device__ __nv_bfloat16 g_w1_lo[128 * K1P];
__device__ __nv_bfloat16 g_w2_hi[512 * 128];
__device__ __nv_bfloat16 g_w2_lo[512 * 128];
__device__ __nv_bfloat16 g_w3_hi[256 * 512];
__device__ __nv_bfloat16 g_w3_lo[256 * 512];

// ---------------------------------------------------------------------------
// helpers
// ---------------------------------------------------------------------------
__device__ __forceinline__ uint32_t smem_u32(const void* p) {
    uint32_t a;
    asm("{ .reg .u64 t; cvta.to.shared.u64 t, %1; cvt.u32.u64 %0, t; }"
        : "=r"(a) : "l"(p));
    return a;
}
#define SWZ128(off) ((off) ^ (((off) >> 3) & 0x70))

#define CP_ASYNC16(saddr, gptr) \
    asm volatile("cp.async.cg.shared.global [%0], [%1], 16;" \
                 :: "r"(saddr), "l"(gptr) : "memory")
#define CP_COMMIT() asm volatile("cp.async.commit_group;" ::: "memory")
#define CP_WAIT0()  asm volatile("cp.async.wait_group 0;" ::: "memory")

#define LDSM_X4(r, addr) \
    asm volatile("ldmatrix.sync.aligned.m8n8.x4.shared.b16 {%0,%1,%2,%3}, [%4];" \
                 : "=r"((r)[0]), "=r"((r)[1]), "=r"((r)[2]), "=r"((r)[3]) \
                 : "r"(addr))

#define MMA_BF16(d, a, b0, b1) \
    asm volatile("mma.sync.aligned.m16n8k16.row.col.f32.bf16.bf16.f32 " \
                 "{%0,%1,%2,%3}, {%4,%5,%6,%7}, {%8,%9}, {%0,%1,%2,%3};" \
                 : "+f"((d)[0]), "+f"((d)[1]), "+f"((d)[2]), "+f"((d)[3]) \
                 : "r"((a)[0]), "r"((a)[1]), "r"((a)[2]), "r"((a)[3]), \
                   "r"(b0), "r"(b1))

__device__ __forceinline__ unsigned pack_bf2(__nv_bfloat16 a, __nv_bfloat16 b) {
    return (unsigned)__bfloat16_as_ushort(a) | ((unsigned)__bfloat16_as_ushort(b) << 16);
}

// ---------------------------------------------------------------------------
// Conv: 3x3 valid conv per sample; writes bf16 hi/lo, K padded to 704.
// ---------------------------------------------------------------------------
#define CONV_S 4
__global__ void conv_kernel(const float* __restrict__ x,
                            const float* __restrict__ wc,
                            __nv_bfloat16* __restrict__ chi,
                            __nv_bfloat16* __restrict__ clo)
{
    __shared__ float xs[CONV_S * 784];
    __shared__ float w[9];
    const int tid  = threadIdx.x;
    const int base = blockIdx.x * CONV_S;

    if (tid < 9) w[tid] = wc[tid];
    #pragma unroll
    for (int i = tid; i < CONV_S * 784; i += 256)
        xs[i] = x[(size_t)base * 784 + i];
    __syncthreads();

    #pragma unroll
    for (int idx = tid; idx < CONV_S * K1P; idx += 256) {
        int s = idx / K1P;
        int o = idx - s * K1P;
        float sum = 0.f;
        if (o < 676) {
            int oi = o / 26;
            int oj = o - oi * 26;
            const float* p = &xs[s * 784 + oi * 28 + oj];
            sum = p[0]  * w[0] + p[1]  * w[1] + p[2]  * w[2]
                + p[28] * w[3] + p[29] * w[4] + p[30] * w[5]
                + p[56] * w[6] + p[57] * w[7] + p[58] * w[8];
        }
        __nv_bfloat16 h = __float2bfloat16(sum);
        size_t g = (size_t)base * K1P + idx;
        chi[g] = h;
        clo[g] = __float2bfloat16(sum - __bfloat162float(h));
    }
}

// ---------------------------------------------------------------------------
// Weight split: fp32 [N,Ks] -> bf16 hi/lo [N,Kd] zero-padded.
// ---------------------------------------------------------------------------
__global__ void wconv_kernel(const float* __restrict__ src, int N, int Ks, int Kd,
                             __nv_bfloat16* __restrict__ hi,
                             __nv_bfloat16* __restrict__ lo)
{
    int i = blockIdx.x * blockDim.x + threadIdx.x;
    if (i >= N * Kd) return;
    int n = i / Kd, k = i - n * Kd;
    float v = (k < Ks) ? src[(size_t)n * Ks + k] : 0.f;
    __nv_bfloat16 h = __float2bfloat16(v);
    hi[i] = h;
    lo[i] = __float2bfloat16(v - __bfloat162float(h));
}

// ---------------------------------------------------------------------------
// mma.sync split-bf16 GEMM: C[m,n] = act( sum_k A[m,k]*W[n,k] + bias[n] )
// CTA: 128x128 tile, 8 warps (64x32 each), BK=64, double-buffered cp.async.
// SPLIT=true: write bf16 hi/lo; SPLIT=false: write fp32 to outHi.
// Requires: M%128==0, N%128==0, K%64==0.
// ---------------------------------------------------------------------------
#define SM_A_HI 0
#define SM_A_LO 16384
#define SM_B_HI 32768
#define SM_B_LO 49152
#define BUF_STRIDE 65536
#define SM_BIAS (2 * BUF_STRIDE)
#define SMEM_SZ (SM_BIAS + 512)

template <bool RELU, bool SPLIT>
__global__ void __launch_bounds__(256)
gemm_mma(const __nv_bfloat16* __restrict__ Ah, const __nv_bfloat16* __restrict__ Al,
         const __nv_bfloat16* __restrict__ Bh, const __nv_bfloat16* __restrict__ Bl,
         const float* __restrict__ bias,
         void* __restrict__ outHi, void* __restrict__ outLo,
         int N, int K)
{
    extern __shared__ __align__(1024) char smem[];
    const uint32_t sb = smem_u32(smem);
    const int tid  = threadIdx.x;
    const int wid  = tid >> 5;
    const int lane = tid & 31;
    const int m0   = blockIdx.y * 128;
    const int n0   = blockIdx.x * 128;
    float* bs = (float*)(smem + SM_BIAS);

    if (tid < 128) bs[tid] = bias[n0 + tid];

    // ---- loader addressing: 128 rows x 64 bf16 (128B rows, SW128) ----
    const int lr = tid >> 3;          // 0..31 (+32 per iter)
    const int lc = tid & 7;           // 16B chunk
    const size_t aBase = (size_t)(m0 + lr) * K + lc * 8;
    const size_t bBase = (size_t)(n0 + lr) * K + lc * 8;
    uint32_t so[4];
    #pragma unroll
    for (int i = 0; i < 4; ++i)
        so[i] = SWZ128((uint32_t)(lr + 32 * i) * 128 + lc * 16);

    // prefetch tile 0 into buffer 0
    #pragma unroll
    for (int i = 0; i < 4; ++i) {
        const size_t ga = aBase + (size_t)(32 * i) * K;
        const size_t gb = bBase + (size_t)(32 * i) * K;
        CP_ASYNC16(sb + SM_A_HI + so[i], Ah + ga);
        CP_ASYNC16(sb + SM_A_LO + so[i], Al + ga);
        CP_ASYNC16(sb + SM_B_HI + so[i], Bh + gb);
        CP_ASYNC16(sb + SM_B_LO + so[i], Bl + gb);
    }
    CP_COMMIT();

    // ---- warp tiling: wm in {0,1} (64 rows), wn in {0..3} (32 cols) ----
    const int wm = wid & 1;
    const int wn = wid >> 1;
    const int lrow  = lane & 15;             // ldmatrix row within 16
    const int lhalf = (lane >> 4) * 16;      // k-half byte offset

    float acc[4][4][4];
    #pragma unroll
    for (int mi = 0; mi < 4; ++mi)
        #pragma unroll
        for (int nj = 0; nj < 4; ++nj)
            #pragma unroll
            for (int q = 0; q < 4; ++q) acc[mi][nj][q] = 0.f;

    int buf = 0;
    for (int kt = 0; kt < K; kt += 64) {
        CP_WAIT0();
        __syncthreads();

        if (kt + 64 < K) {
            const uint32_t nb = sb + (buf ^ 1) * BUF_STRIDE;
            #pragma unroll
            for (int i = 0; i < 4; ++i) {
                const size_t ga = aBase + (size_t)(32 * i) * K + kt + 64;
                const size_t gb = bBase + (size_t)(32 * i) * K + kt + 64;
                CP_ASYNC16(nb + SM_A_HI + so[i], Ah + ga);
                CP_ASYNC16(nb + SM_A_LO + so[i], Al + ga);
                CP_ASYNC16(nb + SM_B_HI + so[i], Bh + gb);
                CP_ASYNC16(nb + SM_B_LO + so[i], Bl + gb);
            }
            CP_COMMIT();
        }

        const uint32_t cb = sb + buf * BUF_STRIDE;
        #pragma unroll
        for (int ks = 0; ks < 4; ++ks) {
            const uint32_t kbyte = ks * 32 + lhalf;
            uint32_t ah[4][4], al[4][4];
            #pragma unroll
            for (int mi = 0; mi < 4; ++mi) {
                const uint32_t row = wm * 64 + mi * 16 + lrow;
                const uint32_t off = SWZ128(row * 128 + kbyte);
                LDSM_X4(ah[mi], cb + SM_A_HI + off);
                LDSM_X4(al[mi], cb + SM_A_LO + off);
            }
            uint32_t bh[2][4], bl[2][4];
            #pragma unroll
            for (int g = 0; g < 2; ++g) {
                const uint32_t row = wn * 32 + g * 16 + lrow;
                const uint32_t off = SWZ128(row * 128 + kbyte);
                LDSM_X4(bh[g], cb + SM_B_HI + off);
                LDSM_X4(bl[g], cb + SM_B_LO + off);
            }
            #pragma unroll
            for (int mi = 0; mi < 4; ++mi) {
                #pragma unroll
                for (int nj = 0; nj < 4; ++nj) {
                    const int g = nj >> 1, h = nj & 1;
                    MMA_BF16(acc[mi][nj], ah[mi], bh[g][h], bh[g][h + 2]);
                    MMA_BF16(acc[mi][nj], al[mi], bh[g][h], bh[g][h + 2]);
                    MMA_BF16(acc[mi][nj], ah[mi], bl[g][h], bl[g][h + 2]);
                }
            }
        }
        __syncthreads();
        buf ^= 1;
    }

    // ---- epilogue: bias (+relu), direct global stores ----
    const int qr = lane >> 2;          // 0..7
    const int qc = (lane & 3) * 2;     // 0,2,4,6
    #pragma unroll
    for (int mi = 0; mi < 4; ++mi) {
        #pragma unroll
        for (int nj = 0; nj < 4; ++nj) {
            const int col = wn * 32 + nj * 8 + qc;
            const float b0 = bs[col], b1 = bs[col + 1];
            #pragma unroll
            for (int half = 0; half < 2; ++half) {
                const int row = wm * 64 + mi * 16 + qr + half * 8;
                float v0 = acc[mi][nj][half * 2 + 0] + b0;
                float v1 = acc[mi][nj][half * 2 + 1] + b1;
                if (RELU) { v0 = fmaxf(v0, 0.f); v1 = fmaxf(v1, 0.f); }
                const size_t g = (size_t)(m0 + row) * N + n0 + col;
                if (SPLIT) {
                    __nv_bfloat16 h0 = __float2bfloat16(v0);
                    __nv_bfloat16 h1 = __float2bfloat16(v1);
                    *(uint32_t*)((__nv_bfloat16*)outHi + g) = pack_bf2(h0, h1);
                    __nv_bfloat16 l0 = __float2bfloat16(v0 - __bfloat162float(h0));
                    __nv_bfloat16 l1 = __float2bfloat16(v1 - __bfloat162float(h1));
                    *(uint32_t*)((__nv_bfloat16*)outLo + g) = pack_bf2(l0, l1);
                } else {
                    *(float2*)((float*)outHi + g) = make_float2(v0, v1);
                }
            }
        }
    }
}

// ---------------------------------------------------------------------------
// Head: out[m,0..9] = h3[m,:] @ w4^T + b4 (K=256, N=10). fp32 input.
// ---------------------------------------------------------------------------
__global__ __launch_bounds__(256)
void head_kernel(const float* __restrict__ h3,
                 const float* __restrict__ w4,
                 const float* __restrict__ b4,
                 float* __restrict__ out)
{
    __shared__ float ws[10 * 256];
    __shared__ float bsh[10];
    const int tid = threadIdx.x;
    #pragma unroll
    for (int i = tid; i < 2560; i += 256) ws[i] = w4[i];
    if (tid < 10) bsh[tid] = b4[tid];
    __syncthreads();

    const int warp = tid >> 5;
    const int lane = tid & 31;
    const int row  = blockIdx.x * 8 + warp;

    float acc[10];
    #pragma unroll
    for (int j = 0; j < 10; ++j) acc[j] = 0.f;

    const float* hr = h3 + (size_t)row * 256;
    #pragma unroll
    for (int t = 0; t < 8; ++t) {
        float xv = hr[t * 32 + lane];
        #pragma unroll
        for (int j = 0; j < 10; ++j)
            acc[j] = fmaf(xv, ws[j * 256 + t * 32 + lane], acc[j]);
    }
    #pragma unroll
    for (int j = 0; j < 10; ++j) {
        #pragma unroll
        for (int off = 16; off > 0; off >>= 1)
            acc[j] += __shfl_xor_sync(0xffffffffu, acc[j], off);
    }
    if (lane == 0) {
        #pragma unroll
        for (int j = 0; j < 10; ++j)
            out[(size_t)row * 10 + j] = acc[j] + bsh[j];
    }
}

// ---------------------------------------------------------------------------
// Launch
// ---------------------------------------------------------------------------
extern "C" void kernel_launch(void* const* d_in, const int* in_sizes, int n_in,
                              void* d_out, int out_size)
{
    const float* x  = (const float*)d_in[0];
    const float* wc = (const float*)d_in[1];
    const float* w1 = (const float*)d_in[2];
    const float* b1 = (const float*)d_in[3];
    const float* w2 = (const float*)d_in[4];
    const float* b2 = (const float*)d_in[5];
    const float* w3 = (const float*)d_in[6];
    const float* b3 = (const float*)d_in[7];
    const float* w4 = (const float*)d_in[8];
    const float* b4 = (const float*)d_in[9];
    float* out = (float*)d_out;

    __nv_bfloat16 *chi, *clo, *h1h, *h1l, *h2h, *h2l;
    __nv_bfloat16 *w1h, *w1l, *w2h, *w2l, *w3h, *w3l;
    float* h3;
    cudaGetSymbolAddress((void**)&chi, g_c_hi);
    cudaGetSymbolAddress((void**)&clo, g_c_lo);
    cudaGetSymbolAddress((void**)&h1h, g_h1_hi);
    cudaGetSymbolAddress((void**)&h1l, g_h1_lo);
    cudaGetSymbolAddress((void**)&h2h, g_h2_hi);
    cudaGetSymbolAddress((void**)&h2l, g_h2_lo);
    cudaGetSymbolAddress((void**)&h3,  g_h3);
    cudaGetSymbolAddress((void**)&w1h, g_w1_hi);
    cudaGetSymbolAddress((void**)&w1l, g_w1_lo);
    cudaGetSymbolAddress((void**)&w2h, g_w2_hi);
    cudaGetSymbolAddress((void**)&w2l, g_w2_lo);
    cudaGetSymbolAddress((void**)&w3h, g_w3_hi);
    cudaGetSymbolAddress((void**)&w3l, g_w3_lo);

    cudaFuncSetAttribute(gemm_mma<true, true>,
                         cudaFuncAttributeMaxDynamicSharedMemorySize, SMEM_SZ);
    cudaFuncSetAttribute(gemm_mma<true, false>,
                         cudaFuncAttributeMaxDynamicSharedMemorySize, SMEM_SZ);

    wconv_kernel<<<(128 * K1P + 255) / 256, 256>>>(w1, 128, 676, K1P, w1h, w1l);
    wconv_kernel<<<(512 * 128 + 255) / 256, 256>>>(w2, 512, 128, 128, w2h, w2l);
    wconv_kernel<<<(256 * 512 + 255) / 256, 256>>>(w3, 256, 512, 512, w3h, w3l);

    conv_kernel<<<BATCH / CONV_S, 256>>>(x, wc, chi, clo);

    // L1: [B,704] x [128,704]^T -> relu -> h1 (split)
    gemm_mma<true, true><<<dim3(1, BATCH / 128), 256, SMEM_SZ>>>(
        chi, clo, w1h, w1l, b1, h1h, h1l, 128, K1P);
    // L2: [B,128] x [512,128]^T -> relu -> h2 (split)
    gemm_mma<true, true><<<dim3(4, BATCH / 128), 256, SMEM_SZ>>>(
        h1h, h1l, w2h, w2l, b2, h2h, h2l, 512, 128);
    // L3: [B,512] x [256,512]^T -> relu -> h3 (fp32)
    gemm_mma<true, false><<<dim3(2, BATCH / 128), 256, SMEM_SZ>>>(
        h2h, h2l, w3h, w3l, b3, h3, nullptr, 256, 512);
    // L4
    head_kernel<<<BATCH / 8, 256>>>(h3, w4, b4, out);
}

// round 5
// speedup vs baseline: 2.1625x; 1.1445x over previous
#include <cuda_runtime.h>
#include <cuda_bf16.h>
#include <cstdint>

// ---------------------------------------------------------------------------
// DigitConvolutionalModel via mma.sync bf16 split-precision (bf16x3) GEMMs.
// R5: shuffle-based conv (no smem input staging, vectorized stores) +
//     64x128 GEMM tiles (97KB smem -> 2 CTAs/SM for latency hiding).
// ---------------------------------------------------------------------------

#define BATCH 65536
#define K1P   704

// ---- scratch (__device__ globals; no allocations allowed) ----
__device__ __nv_bfloat16 g_c_hi [BATCH * K1P];
__device__ __nv_bfloat16 g_c_lo [BATCH * K1P];
__device__ __nv_bfloat16 g_h1_hi[BATCH * 128];
__device__ __nv_bfloat16 g_h1_lo[BATCH * 128];
__device__ __nv_bfloat16 g_h2_hi[BATCH * 512];
__device__ __nv_bfloat16 g_h2_lo[BATCH * 512];
__device__ float         g_h3   [BATCH * 256];
__device__ __nv_bfloat16 g_w1_hi[128 * K1P];
__device__ __nv_bfloat16 g_w1_lo[128 * K1P];
__device__ __nv_bfloat16 g_w2_hi[512 * 128];
__device__ __nv_bfloat16 g_w2_lo[512 * 128];
__device__ __nv_bfloat16 g_w3_hi[256 * 512];
__device__ __nv_bfloat16 g_w3_lo[256 * 512];

// ---------------------------------------------------------------------------
// helpers
// ---------------------------------------------------------------------------
__device__ __forceinline__ uint32_t smem_u32(const void* p) {
    uint32_t a;
    asm("{ .reg .u64 t; cvta.to.shared.u64 t, %1; cvt.u32.u64 %0, t; }"
        : "=r"(a) : "l"(p));
    return a;
}
#define SWZ128(off) ((off) ^ (((off) >> 3) & 0x70))

#define CP_ASYNC16(saddr, gptr) \
    asm volatile("cp.async.cg.shared.global [%0], [%1], 16;" \
                 :: "r"(saddr), "l"(gptr) : "memory")
#define CP_COMMIT() asm volatile("cp.async.commit_group;" ::: "memory")
#define CP_WAIT0()  asm volatile("cp.async.wait_group 0;" ::: "memory")

#define LDSM_X4(r, addr) \
    asm volatile("ldmatrix.sync.aligned.m8n8.x4.shared.b16 {%0,%1,%2,%3}, [%4];" \
                 : "=r"((r)[0]), "=r"((r)[1]), "=r"((r)[2]), "=r"((r)[3]) \
                 : "r"(addr))

#define MMA_BF16(d, a, b0, b1) \
    asm volatile("mma.sync.aligned.m16n8k16.row.col.f32.bf16.bf16.f32 " \
                 "{%0,%1,%2,%3}, {%4,%5,%6,%7}, {%8,%9}, {%0,%1,%2,%3};" \
                 : "+f"((d)[0]), "+f"((d)[1]), "+f"((d)[2]), "+f"((d)[3]) \
                 : "r"((a)[0]), "r"((a)[1]), "r"((a)[2]), "r"((a)[3]), \
                   "r"(b0), "r"(b1))

__device__ __forceinline__ unsigned pack_bf2(__nv_bfloat16 a, __nv_bfloat16 b) {
    return (unsigned)__bfloat16_as_ushort(a) | ((unsigned)__bfloat16_as_ushort(b) << 16);
}

// ---------------------------------------------------------------------------
// Conv v2: one warp per sample. Rolling 3-row register window; shifted taps
// via shfl_down; outputs staged in smem, copied out as uint4.
// ---------------------------------------------------------------------------
__global__ void __launch_bounds__(256)
conv_kernel(const float* __restrict__ x,
            const float* __restrict__ wc,
            __nv_bfloat16* __restrict__ chi,
            __nv_bfloat16* __restrict__ clo)
{
    __shared__ float wsh[9];
    __shared__ __align__(16) __nv_bfloat16 ohi[8][704];
    __shared__ __align__(16) __nv_bfloat16 olo[8][704];

    const int tid  = threadIdx.x;
    const int wid  = tid >> 5;
    const int lane = tid & 31;
    const int s    = blockIdx.x * 8 + wid;

    if (tid < 9) wsh[tid] = wc[tid];
    __syncthreads();

    const float w0 = wsh[0], w1 = wsh[1], w2 = wsh[2];
    const float w3 = wsh[3], w4 = wsh[4], w5 = wsh[5];
    const float w6 = wsh[6], w7 = wsh[7], w8 = wsh[8];

    const float* xr = x + (size_t)s * 784;
    float a = (lane < 28) ? xr[lane]      : 0.f;
    float b = (lane < 28) ? xr[28 + lane] : 0.f;

    #pragma unroll 1
    for (int oi = 0; oi < 26; ++oi) {
        float c = (lane < 28) ? xr[(oi + 2) * 28 + lane] : 0.f;
        float a1 = __shfl_down_sync(0xffffffffu, a, 1);
        float a2 = __shfl_down_sync(0xffffffffu, a, 2);
        float b1 = __shfl_down_sync(0xffffffffu, b, 1);
        float b2 = __shfl_down_sync(0xffffffffu, b, 2);
        float c1 = __shfl_down_sync(0xffffffffu, c, 1);
        float c2 = __shfl_down_sync(0xffffffffu, c, 2);
        float sum = a * w0; sum = fmaf(a1, w1, sum); sum = fmaf(a2, w2, sum);
        sum = fmaf(b, w3, sum); sum = fmaf(b1, w4, sum); sum = fmaf(b2, w5, sum);
        sum = fmaf(c, w6, sum); sum = fmaf(c1, w7, sum); sum = fmaf(c2, w8, sum);
        if (lane < 26) {
            __nv_bfloat16 h = __float2bfloat16(sum);
            ohi[wid][oi * 26 + lane] = h;
            olo[wid][oi * 26 + lane] = __float2bfloat16(sum - __bfloat162float(h));
        }
        a = b; b = c;
    }
    // zero pad 676..703
    if (lane < 28) {
        ohi[wid][676 + lane] = __float2bfloat16(0.f);
        olo[wid][676 + lane] = __float2bfloat16(0.f);
    }
    __syncwarp();

    const size_t base = (size_t)s * K1P;
    uint4* gh = (uint4*)(chi + base);
    uint4* gl = (uint4*)(clo + base);
    const uint4* sh = (const uint4*)ohi[wid];
    const uint4* sl = (const uint4*)olo[wid];
    #pragma unroll
    for (int i = lane; i < 88; i += 32) {
        gh[i] = sh[i];
        gl[i] = sl[i];
    }
}

// ---------------------------------------------------------------------------
// Weight split: fp32 [N,Ks] -> bf16 hi/lo [N,Kd] zero-padded.
// ---------------------------------------------------------------------------
__global__ void wconv_kernel(const float* __restrict__ src, int N, int Ks, int Kd,
                             __nv_bfloat16* __restrict__ hi,
                             __nv_bfloat16* __restrict__ lo)
{
    int i = blockIdx.x * blockDim.x + threadIdx.x;
    if (i >= N * Kd) return;
    int n = i / Kd, k = i - n * Kd;
    float v = (k < Ks) ? src[(size_t)n * Ks + k] : 0.f;
    __nv_bfloat16 h = __float2bfloat16(v);
    hi[i] = h;
    lo[i] = __float2bfloat16(v - __bfloat162float(h));
}

// ---------------------------------------------------------------------------
// mma.sync split-bf16 GEMM: C[m,n] = act( sum_k A[m,k]*W[n,k] + bias[n] )
// CTA: 64x128 tile, 8 warps (32x32 each), BK=64, double-buffered cp.async.
// ~97KB smem -> 2 CTAs/SM. SPLIT=true: bf16 hi/lo out; else fp32 out.
// Requires: M%64==0, N%128==0, K%64==0.
// ---------------------------------------------------------------------------
#define SM_A_HI 0
#define SM_A_LO 8192
#define SM_B_HI 16384
#define SM_B_LO 32768
#define BUF_STRIDE 49152
#define SM_BIAS (2 * BUF_STRIDE)
#define SMEM_SZ (SM_BIAS + 512)

template <bool RELU, bool SPLIT>
__global__ void __launch_bounds__(256, 2)
gemm_mma(const __nv_bfloat16* __restrict__ Ah, const __nv_bfloat16* __restrict__ Al,
         const __nv_bfloat16* __restrict__ Bh, const __nv_bfloat16* __restrict__ Bl,
         const float* __restrict__ bias,
         void* __restrict__ outHi, void* __restrict__ outLo,
         int N, int K)
{
    extern __shared__ __align__(1024) char smem[];
    const uint32_t sb = smem_u32(smem);
    const int tid  = threadIdx.x;
    const int wid  = tid >> 5;
    const int lane = tid & 31;
    const int m0   = blockIdx.y * 64;
    const int n0   = blockIdx.x * 128;
    float* bs = (float*)(smem + SM_BIAS);

    if (tid < 128) bs[tid] = bias[n0 + tid];

    // ---- loader addressing: rows x 64 bf16 (128B rows, SW128) ----
    const int lr = tid >> 3;          // 0..31
    const int lc = tid & 7;           // 16B chunk
    const size_t aBase = (size_t)(m0 + lr) * K + lc * 8;
    const size_t bBase = (size_t)(n0 + lr) * K + lc * 8;
    uint32_t so[4];
    #pragma unroll
    for (int i = 0; i < 4; ++i)
        so[i] = SWZ128((uint32_t)(lr + 32 * i) * 128 + lc * 16);

    // prefetch tile 0 into buffer 0  (A: 64 rows, B: 128 rows)
    #pragma unroll
    for (int i = 0; i < 2; ++i) {
        const size_t ga = aBase + (size_t)(32 * i) * K;
        CP_ASYNC16(sb + SM_A_HI + so[i], Ah + ga);
        CP_ASYNC16(sb + SM_A_LO + so[i], Al + ga);
    }
    #pragma unroll
    for (int i = 0; i < 4; ++i) {
        const size_t gb = bBase + (size_t)(32 * i) * K;
        CP_ASYNC16(sb + SM_B_HI + so[i], Bh + gb);
        CP_ASYNC16(sb + SM_B_LO + so[i], Bl + gb);
    }
    CP_COMMIT();

    // ---- warp tiling: wm in {0,1} (32 rows), wn in {0..3} (32 cols) ----
    const int wm = wid & 1;
    const int wn = wid >> 1;
    const int lrow  = lane & 15;
    const int lhalf = (lane >> 4) * 16;

    float acc[2][4][4];
    #pragma unroll
    for (int mi = 0; mi < 2; ++mi)
        #pragma unroll
        for (int nj = 0; nj < 4; ++nj)
            #pragma unroll
            for (int q = 0; q < 4; ++q) acc[mi][nj][q] = 0.f;

    int buf = 0;
    for (int kt = 0; kt < K; kt += 64) {
        CP_WAIT0();
        __syncthreads();

        if (kt + 64 < K) {
            const uint32_t nb = sb + (buf ^ 1) * BUF_STRIDE;
            #pragma unroll
            for (int i = 0; i < 2; ++i) {
                const size_t ga = aBase + (size_t)(32 * i) * K + kt + 64;
                CP_ASYNC16(nb + SM_A_HI + so[i], Ah + ga);
                CP_ASYNC16(nb + SM_A_LO + so[i], Al + ga);
            }
            #pragma unroll
            for (int i = 0; i < 4; ++i) {
                const size_t gb = bBase + (size_t)(32 * i) * K + kt + 64;
                CP_ASYNC16(nb + SM_B_HI + so[i], Bh + gb);
                CP_ASYNC16(nb + SM_B_LO + so[i], Bl + gb);
            }
            CP_COMMIT();
        }

        const uint32_t cb = sb + buf * BUF_STRIDE;
        #pragma unroll
        for (int ks = 0; ks < 4; ++ks) {
            const uint32_t kbyte = ks * 32 + lhalf;
            uint32_t ah[2][4], al[2][4];
            #pragma unroll
            for (int mi = 0; mi < 2; ++mi) {
                const uint32_t row = wm * 32 + mi * 16 + lrow;
                const uint32_t off = SWZ128(row * 128 + kbyte);
                LDSM_X4(ah[mi], cb + SM_A_HI + off);
                LDSM_X4(al[mi], cb + SM_A_LO + off);
            }
            uint32_t bh[2][4], bl[2][4];
            #pragma unroll
            for (int g = 0; g < 2; ++g) {
                const uint32_t row = wn * 32 + g * 16 + lrow;
                const uint32_t off = SWZ128(row * 128 + kbyte);
                LDSM_X4(bh[g], cb + SM_B_HI + off);
                LDSM_X4(bl[g], cb + SM_B_LO + off);
            }
            #pragma unroll
            for (int mi = 0; mi < 2; ++mi) {
                #pragma unroll
                for (int nj = 0; nj < 4; ++nj) {
                    const int g = nj >> 1, h = nj & 1;
                    MMA_BF16(acc[mi][nj], ah[mi], bh[g][h], bh[g][h + 2]);
                    MMA_BF16(acc[mi][nj], al[mi], bh[g][h], bh[g][h + 2]);
                    MMA_BF16(acc[mi][nj], ah[mi], bl[g][h], bl[g][h + 2]);
                }
            }
        }
        __syncthreads();
        buf ^= 1;
    }

    // ---- epilogue: bias (+relu), direct global stores ----
    const int qr = lane >> 2;
    const int qc = (lane & 3) * 2;
    #pragma unroll
    for (int mi = 0; mi < 2; ++mi) {
        #pragma unroll
        for (int nj = 0; nj < 4; ++nj) {
            const int col = wn * 32 + nj * 8 + qc;
            const float b0 = bs[col], b1 = bs[col + 1];
            #pragma unroll
            for (int half = 0; half < 2; ++half) {
                const int row = wm * 32 + mi * 16 + qr + half * 8;
                float v0 = acc[mi][nj][half * 2 + 0] + b0;
                float v1 = acc[mi][nj][half * 2 + 1] + b1;
                if (RELU) { v0 = fmaxf(v0, 0.f); v1 = fmaxf(v1, 0.f); }
                const size_t g = (size_t)(m0 + row) * N + n0 + col;
                if (SPLIT) {
                    __nv_bfloat16 h0 = __float2bfloat16(v0);
                    __nv_bfloat16 h1 = __float2bfloat16(v1);
                    *(uint32_t*)((__nv_bfloat16*)outHi + g) = pack_bf2(h0, h1);
                    __nv_bfloat16 l0 = __float2bfloat16(v0 - __bfloat162float(h0));
                    __nv_bfloat16 l1 = __float2bfloat16(v1 - __bfloat162float(h1));
                    *(uint32_t*)((__nv_bfloat16*)outLo + g) = pack_bf2(l0, l1);
                } else {
                    *(float2*)((float*)outHi + g) = make_float2(v0, v1);
                }
            }
        }
    }
}

// ---------------------------------------------------------------------------
// Head: out[m,0..9] = h3[m,:] @ w4^T + b4 (K=256, N=10). fp32 input.
// ---------------------------------------------------------------------------
__global__ void __launch_bounds__(256)
head_kernel(const float* __restrict__ h3,
            const float* __restrict__ w4,
            const float* __restrict__ b4,
            float* __restrict__ out)
{
    __shared__ float ws[10 * 256];
    __shared__ float bsh[10];
    const int tid = threadIdx.x;
    #pragma unroll
    for (int i = tid; i < 2560; i += 256) ws[i] = w4[i];
    if (tid < 10) bsh[tid] = b4[tid];
    __syncthreads();

    const int warp = tid >> 5;
    const int lane = tid & 31;
    const int row  = blockIdx.x * 8 + warp;

    float acc[10];
    #pragma unroll
    for (int j = 0; j < 10; ++j) acc[j] = 0.f;

    const float* hr = h3 + (size_t)row * 256;
    #pragma unroll
    for (int t = 0; t < 8; ++t) {
        float xv = hr[t * 32 + lane];
        #pragma unroll
        for (int j = 0; j < 10; ++j)
            acc[j] = fmaf(xv, ws[j * 256 + t * 32 + lane], acc[j]);
    }
    #pragma unroll
    for (int j = 0; j < 10; ++j) {
        #pragma unroll
        for (int off = 16; off > 0; off >>= 1)
            acc[j] += __shfl_xor_sync(0xffffffffu, acc[j], off);
    }
    if (lane == 0) {
        #pragma unroll
        for (int j = 0; j < 10; ++j)
            out[(size_t)row * 10 + j] = acc[j] + bsh[j];
    }
}

// ---------------------------------------------------------------------------
// Launch
// ---------------------------------------------------------------------------
extern "C" void kernel_launch(void* const* d_in, const int* in_sizes, int n_in,
                              void* d_out, int out_size)
{
    const float* x  = (const float*)d_in[0];
    const float* wc = (const float*)d_in[1];
    const float* w1 = (const float*)d_in[2];
    const float* b1 = (const float*)d_in[3];
    const float* w2 = (const float*)d_in[4];
    const float* b2 = (const float*)d_in[5];
    const float* w3 = (const float*)d_in[6];
    const float* b3 = (const float*)d_in[7];
    const float* w4 = (const float*)d_in[8];
    const float* b4 = (const float*)d_in[9];
    float* out = (float*)d_out;

    __nv_bfloat16 *chi, *clo, *h1h, *h1l, *h2h, *h2l;
    __nv_bfloat16 *w1h, *w1l, *w2h, *w2l, *w3h, *w3l;
    float* h3;
    cudaGetSymbolAddress((void**)&chi, g_c_hi);
    cudaGetSymbolAddress((void**)&clo, g_c_lo);
    cudaGetSymbolAddress((void**)&h1h, g_h1_hi);
    cudaGetSymbolAddress((void**)&h1l, g_h1_lo);
    cudaGetSymbolAddress((void**)&h2h, g_h2_hi);
    cudaGetSymbolAddress((void**)&h2l, g_h2_lo);
    cudaGetSymbolAddress((void**)&h3,  g_h3);
    cudaGetSymbolAddress((void**)&w1h, g_w1_hi);
    cudaGetSymbolAddress((void**)&w1l, g_w1_lo);
    cudaGetSymbolAddress((void**)&w2h, g_w2_hi);
    cudaGetSymbolAddress((void**)&w2l, g_w2_lo);
    cudaGetSymbolAddress((void**)&w3h, g_w3_hi);
    cudaGetSymbolAddress((void**)&w3l, g_w3_lo);

    cudaFuncSetAttribute(gemm_mma<true, true>,
                         cudaFuncAttributeMaxDynamicSharedMemorySize, SMEM_SZ);
    cudaFuncSetAttribute(gemm_mma<true, false>,
                         cudaFuncAttributeMaxDynamicSharedMemorySize, SMEM_SZ);

    wconv_kernel<<<(128 * K1P + 255) / 256, 256>>>(w1, 128, 676, K1P, w1h, w1l);
    wconv_kernel<<<(512 * 128 + 255) / 256, 256>>>(w2, 512, 128, 128, w2h, w2l);
    wconv_kernel<<<(256 * 512 + 255) / 256, 256>>>(w3, 256, 512, 512, w3h, w3l);

    conv_kernel<<<BATCH / 8, 256>>>(x, wc, chi, clo);

    // L1: [B,704] x [128,704]^T -> relu -> h1 (split)
    gemm_mma<true, true><<<dim3(1, BATCH / 64), 256, SMEM_SZ>>>(
        chi, clo, w1h, w1l, b1, h1h, h1l, 128, K1P);
    // L2: [B,128] x [512,128]^T -> relu -> h2 (split)
    gemm_mma<true, true><<<dim3(4, BATCH / 64), 256, SMEM_SZ>>>(
        h1h, h1l, w2h, w2l, b2, h2h, h2l, 512, 128);
    // L3: [B,512] x [256,512]^T -> relu -> h3 (fp32)
    gemm_mma<true, false><<<dim3(2, BATCH / 64), 256, SMEM_SZ>>>(
        h2h, h2l, w3h, w3l, b3, h3, nullptr, 256, 512);
    // L4
    head_kernel<<<BATCH / 8, 256>>>(h3, w4, b4, out);
}